// round 2
// baseline (speedup 1.0000x reference)
#include <cuda_runtime.h>

#define NN   100000
#define EE   600000
#define HIDC 128
#define OUTC 40
#define GG   64
#define NB_SCAN 98   // ceil(100000/1024)

// ---------------- persistent scratch (static device arrays; no allocation) ----
__device__ float g_m [NN*HIDC];   // lin_r output (messages)
__device__ float g_hl[NN*HIDC];   // lin_l output, then h2 (normalized)
__device__ float g_h [NN*HIDC];   // layer output h
__device__ int   g_off[NN+1];     // CSR offsets by dst
__device__ int   g_cur[NN];       // fill cursors
__device__ int   g_eid[EE];       // CSR src ids
__device__ int   g_bsum[NB_SCAN];
__device__ int   g_bofs[NB_SCAN];
__device__ float g_colsum [HIDC];
__device__ float g_colsum2[HIDC];
__device__ float g_mu  [HIDC];
__device__ float g_rstd[HIDC];
__device__ float g_pool[GG*HIDC];
__device__ int   g_gs[GG+1];      // per-graph node range (batch is sorted)

// ---------------- CSR build --------------------------------------------------
__global__ void k_zero_off() {
    int i = blockIdx.x*blockDim.x + threadIdx.x;
    if (i <= NN) g_off[i] = 0;
}

__global__ void k_hist(const int* __restrict__ dst) {
    int e = blockIdx.x*blockDim.x + threadIdx.x;
    if (e < EE) atomicAdd(&g_off[dst[e]], 1);
}

__global__ void k_scan1() {
    __shared__ int s[1024];
    int t = threadIdx.x;
    int i = blockIdx.x*1024 + t;
    int v = (i < NN) ? g_off[i] : 0;
    s[t] = v;
    __syncthreads();
    for (int o = 1; o < 1024; o <<= 1) {
        int x = (t >= o) ? s[t-o] : 0;
        __syncthreads();
        s[t] += x;
        __syncthreads();
    }
    int incl = s[t];
    if (i < NN) g_off[i] = incl - v;     // exclusive within block
    if (t == 1023) g_bsum[blockIdx.x] = incl;
}

__global__ void k_scan2() {
    int run = 0;
    for (int b = 0; b < NB_SCAN; ++b) { g_bofs[b] = run; run += g_bsum[b]; }
}

__global__ void k_scan3() {
    int i = blockIdx.x*blockDim.x + threadIdx.x;
    if (i < NN) {
        int o = g_off[i] + g_bofs[i >> 10];
        g_off[i] = o;
        g_cur[i] = o;
    }
    if (i == 0) g_off[NN] = EE;
}

__global__ void k_fill(const int* __restrict__ src, const int* __restrict__ dst) {
    int e = blockIdx.x*blockDim.x + threadIdx.x;
    if (e < EE) {
        int d = dst[e];
        int p = atomicAdd(&g_cur[d], 1);
        g_eid[p] = src[e];
    }
}

__global__ void k_gstart(const int* __restrict__ batch) {
    int g = threadIdx.x;
    if (g > GG) return;
    if (g == GG) { g_gs[GG] = NN; return; }
    int lo = 0, hi = NN;
    while (lo < hi) { int mid = (lo + hi) >> 1; if (batch[mid] < g) lo = mid + 1; else hi = mid; }
    g_gs[g] = lo;
}

// ---------------- dual GEMM: hl = h@Wl^T+bl ; m = h@Wr^T+br ------------------
// block: 64 rows x 256 cols (128 Wl-cols ++ 128 Wr-cols), 256 threads,
// thread tile 4 rows x 16 cols as 8 f32x2 pairs; fma.rn.f32x2 mainloop.
#define GEMM_SMEM_FLOATS (128*256 + 64*132)
#define GEMM_SMEM_BYTES  (GEMM_SMEM_FLOATS*4)

__global__ __launch_bounds__(256, 1) void k_gemm_dual(
    const float* __restrict__ Ain,
    const float* __restrict__ Wl, const float* __restrict__ Wr,
    const float* __restrict__ bl, const float* __restrict__ br)
{
    extern __shared__ float smem[];
    float* Ws = smem;              // [128][256], col index xor-swizzled by ((k>>2)&15)<<1
    float* As = smem + 128*256;    // [64][132]
    const float* A = Ain ? Ain : g_h;
    int tid = threadIdx.x;
    int r0  = blockIdx.x * 64;

    // load both W matrices, transposed to Ws[k][c] with bank swizzle
    for (int it = 0; it < 32; ++it) {
        int idx = it*256 + tid;
        int c  = idx >> 5;     // 0..255 (warp-uniform)
        int kq = idx & 31;     // float4 index along k
        const float* Wsrc = (c < 128) ? (Wl + c*128 + kq*4) : (Wr + (c-128)*128 + kq*4);
        float4 v = *(const float4*)Wsrc;
        int cs = c ^ ((kq & 15) << 1);
        Ws[(kq*4+0)*256 + cs] = v.x;
        Ws[(kq*4+1)*256 + cs] = v.y;
        Ws[(kq*4+2)*256 + cs] = v.z;
        Ws[(kq*4+3)*256 + cs] = v.w;
    }
    // load A tile (row-major, padded stride 132)
    for (int it = 0; it < 8; ++it) {
        int idx = it*256 + tid;
        int rl = idx >> 5;
        int kq = idx & 31;
        float4 v = make_float4(0.f, 0.f, 0.f, 0.f);
        if (r0 + rl < NN) v = *(const float4*)(A + (r0+rl)*128 + kq*4);
        *(float4*)(As + rl*132 + kq*4) = v;
    }
    __syncthreads();

    int tc = tid & 15, tr = tid >> 4;
    unsigned long long acc[4][8];
    #pragma unroll
    for (int j = 0; j < 8; ++j) {
        int c = j*32 + 2*tc;
        float b0 = (c < 128) ? bl[c]   : br[c-128];
        float b1 = (c < 128) ? bl[c+1] : br[c-127];
        unsigned long long bb;
        asm("mov.b64 %0, {%1,%2};" : "=l"(bb) : "f"(b0), "f"(b1));
        #pragma unroll
        for (int rr = 0; rr < 4; ++rr) acc[rr][j] = bb;
    }

    #pragma unroll 4
    for (int k = 0; k < 128; ++k) {
        int sw = ((k >> 2) & 15) << 1;
        unsigned long long w[8];
        #pragma unroll
        for (int j = 0; j < 8; ++j)
            w[j] = *(const unsigned long long*)(Ws + k*256 + j*32 + ((2*tc) ^ sw));
        #pragma unroll
        for (int rr = 0; rr < 4; ++rr) {
            float a = As[(tr*4+rr)*132 + k];
            unsigned long long a2;
            asm("mov.b64 %0, {%1,%1};" : "=l"(a2) : "f"(a));
            #pragma unroll
            for (int j = 0; j < 8; ++j)
                asm("fma.rn.f32x2 %0, %1, %2, %0;" : "+l"(acc[rr][j]) : "l"(a2), "l"(w[j]));
        }
    }

    #pragma unroll
    for (int rr = 0; rr < 4; ++rr) {
        int row = r0 + tr*4 + rr;
        if (row >= NN) continue;
        #pragma unroll
        for (int j = 0; j < 8; ++j) {
            int c = j*32 + 2*tc;
            float o0, o1;
            asm("mov.b64 {%0,%1}, %2;" : "=f"(o0), "=f"(o1) : "l"(acc[rr][j]));
            float2 v = make_float2(o0, o1);
            if (c < 128) *(float2*)(g_hl + row*128 + c)       = v;
            else         *(float2*)(g_m  + row*128 + (c-128)) = v;
        }
    }
}

// ---------------- per-layer: gather-mean + combine + L2 norm + BN stats ------
__global__ void k_zero_stats() {
    int t = threadIdx.x;
    if (t < 128) { g_colsum[t] = 0.f; g_colsum2[t] = 0.f; }
}

__global__ void k_agg() {
    __shared__ float s1[128], s2[128];
    int tid = threadIdx.x;
    if (tid < 128) { s1[tid] = 0.f; s2[tid] = 0.f; }
    __syncthreads();
    int lane = tid & 31;
    int wid  = blockIdx.x*8 + (tid >> 5);
    int nw   = gridDim.x*8;
    float c1x=0,c1y=0,c1z=0,c1w=0, c2x=0,c2y=0,c2z=0,c2w=0;
    for (int node = wid; node < NN; node += nw) {
        int e0 = g_off[node], e1 = g_off[node+1];
        float ax=0, ay=0, az=0, aw=0;
        for (int e = e0; e < e1; ++e) {
            int srow = g_eid[e];
            float4 v = *(const float4*)(g_m + srow*128 + lane*4);
            ax += v.x; ay += v.y; az += v.z; aw += v.w;
        }
        float inv = 1.f / fmaxf((float)(e1 - e0), 1.f);
        float4 h = *(const float4*)(g_hl + node*128 + lane*4);
        h.x += ax*inv; h.y += ay*inv; h.z += az*inv; h.w += aw*inv;
        float ss = h.x*h.x + h.y*h.y + h.z*h.z + h.w*h.w;
        #pragma unroll
        for (int o = 16; o > 0; o >>= 1) ss += __shfl_xor_sync(0xffffffffu, ss, o);
        float sc = 1.f / fmaxf(sqrtf(ss), 1e-12f);
        h.x *= sc; h.y *= sc; h.z *= sc; h.w *= sc;
        *(float4*)(g_hl + node*128 + lane*4) = h;
        c1x += h.x; c1y += h.y; c1z += h.z; c1w += h.w;
        c2x += h.x*h.x; c2y += h.y*h.y; c2z += h.z*h.z; c2w += h.w*h.w;
    }
    atomicAdd(&s1[lane*4+0], c1x); atomicAdd(&s1[lane*4+1], c1y);
    atomicAdd(&s1[lane*4+2], c1z); atomicAdd(&s1[lane*4+3], c1w);
    atomicAdd(&s2[lane*4+0], c2x); atomicAdd(&s2[lane*4+1], c2y);
    atomicAdd(&s2[lane*4+2], c2z); atomicAdd(&s2[lane*4+3], c2w);
    __syncthreads();
    if (tid < 128) {
        atomicAdd(&g_colsum[tid],  s1[tid]);
        atomicAdd(&g_colsum2[tid], s2[tid]);
    }
}

__global__ void k_bnfin() {
    int t = threadIdx.x;
    const float invn = 1.f / (float)NN;
    float mu = g_colsum[t] * invn;
    float var = g_colsum2[t] * invn - mu*mu;
    g_mu[t] = mu;
    g_rstd[t] = rsqrtf(var + 1e-5f);
}

__global__ void k_bn_apply(const float* __restrict__ gamma, const float* __restrict__ beta) {
    int i = blockIdx.x*blockDim.x + threadIdx.x;
    const int tot = NN*32;           // float4 count
    for (; i < tot; i += gridDim.x*blockDim.x) {
        int c = (i & 31) * 4;
        float4 v = *(const float4*)(g_hl + i*4);
        v.x = fmaxf(gamma[c+0]*(v.x - g_mu[c+0])*g_rstd[c+0] + beta[c+0], 0.f);
        v.y = fmaxf(gamma[c+1]*(v.y - g_mu[c+1])*g_rstd[c+1] + beta[c+1], 0.f);
        v.z = fmaxf(gamma[c+2]*(v.z - g_mu[c+2])*g_rstd[c+2] + beta[c+2], 0.f);
        v.w = fmaxf(gamma[c+3]*(v.w - g_mu[c+3])*g_rstd[c+3] + beta[c+3], 0.f);
        *(float4*)(g_h + i*4) = v;
    }
}

// ---------------- pooling + head ---------------------------------------------
__global__ void k_pool() {
    int g = blockIdx.x, t = threadIdx.x;
    int s = g_gs[g], e = g_gs[g+1];
    float acc = 0.f;
    int node = s;
    for (; node + 16 <= e; node += 16) {
        float p = 0.f;
        #pragma unroll
        for (int j = 0; j < 16; ++j) p += g_h[(node+j)*128 + t];
        acc += p;
    }
    for (; node < e; ++node) acc += g_h[node*128 + t];
    g_pool[g*128 + t] = acc;
}

__global__ void k_head(const float* __restrict__ W1, const float* __restrict__ b1,
                       const float* __restrict__ W2, const float* __restrict__ b2,
                       float* __restrict__ out)
{
    __shared__ float ps[128], us[128], ls[OUTC], st[2];
    int g = blockIdx.x, t = threadIdx.x;
    float cg = (float)(g_gs[g+1] - g_gs[g]);
    ps[t] = g_pool[g*128 + t];
    __syncthreads();
    float u = b1[t] * cg;
    #pragma unroll 8
    for (int k = 0; k < 128; ++k) u += ps[k] * W1[t*128 + k];
    us[t] = u;
    __syncthreads();
    if (t < OUTC) {
        float l = b2[t] * cg;
        #pragma unroll 8
        for (int k = 0; k < 128; ++k) l += us[k] * W2[t*128 + k];
        ls[t] = l;
    }
    __syncthreads();
    if (t == 0) {
        float mx = -1e30f;
        for (int j = 0; j < OUTC; ++j) mx = fmaxf(mx, ls[j]);
        float se = 0.f;
        for (int j = 0; j < OUTC; ++j) se += expf(ls[j] - mx);
        st[0] = mx; st[1] = logf(se);
    }
    __syncthreads();
    if (t < OUTC) out[g*OUTC + t] = ls[t] - st[0] - st[1];
}

// ---------------- launch ------------------------------------------------------
extern "C" void kernel_launch(void* const* d_in, const int* in_sizes, int n_in,
                              void* d_out, int out_size)
{
    const float* x     = (const float*)d_in[0];
    const int*   ei    = (const int*)  d_in[1];
    const int*   batch = (const int*)  d_in[2];
    const float* Wl    = (const float*)d_in[3];
    const float* bl    = (const float*)d_in[4];
    const float* Wr    = (const float*)d_in[5];
    const float* br    = (const float*)d_in[6];
    const float* gamma = (const float*)d_in[7];
    const float* beta  = (const float*)d_in[8];
    const float* W1    = (const float*)d_in[9];
    const float* b1    = (const float*)d_in[10];
    const float* W2    = (const float*)d_in[11];
    const float* b2    = (const float*)d_in[12];
    float* out = (float*)d_out;

    const int* src = ei;
    const int* dst = ei + EE;

    cudaFuncSetAttribute(k_gemm_dual, cudaFuncAttributeMaxDynamicSharedMemorySize,
                         GEMM_SMEM_BYTES);

    // CSR by dst (rebuilt every call; deterministic work)
    k_zero_off<<<391, 256>>>();
    k_hist<<<2344, 256>>>(dst);
    k_scan1<<<NB_SCAN, 1024>>>();
    k_scan2<<<1, 1>>>();
    k_scan3<<<391, 256>>>();
    k_fill<<<2344, 256>>>(src, dst);
    k_gstart<<<1, GG+1>>>(batch);

    for (int i = 0; i < 3; ++i) {
        const float* Ain = (i == 0) ? x : nullptr;   // nullptr -> read g_h
        k_gemm_dual<<<(NN+63)/64, 256, GEMM_SMEM_BYTES>>>(
            Ain, Wl + i*HIDC*HIDC, Wr + i*HIDC*HIDC, bl + i*HIDC, br + i*HIDC);
        k_zero_stats<<<1, 128>>>();
        k_agg<<<1480, 256>>>();
        k_bnfin<<<1, 128>>>();
        k_bn_apply<<<2048, 256>>>(gamma + i*HIDC, beta + i*HIDC);
    }

    k_pool<<<GG, 128>>>();
    k_head<<<GG, 128>>>(W1, b1, W2, b2, out);
}

// round 7
// speedup vs baseline: 1.6008x; 1.6008x over previous
#include <cuda_runtime.h>
#include <cuda_bf16.h>

#define NN   100000
#define EE   600000
#define HIDC 128
#define OUTC 40
#define GG   64
#define NB_SCAN 98   // ceil(100000/1024)

// ---------------- persistent scratch (static device arrays; no allocation) ----
__device__ float g_m [NN*HIDC];   // lin_r output (messages)
__device__ float g_hl[NN*HIDC];   // lin_l output, then h2 (normalized)
__device__ float g_h [NN*HIDC];   // layer output h
__device__ int   g_off[NN+1];     // CSR offsets by dst
__device__ int   g_cur[NN];       // fill cursors
__device__ int   g_eid[EE];       // CSR src ids
__device__ int   g_bsum[NB_SCAN];
__device__ float g_cs1[3*HIDC];   // per-layer BN column sums
__device__ float g_cs2[3*HIDC];
__device__ float g_pool[GG*HIDC];
__device__ int   g_gs[GG+1];      // per-graph node range (batch is sorted)

// ---------------- CSR build --------------------------------------------------
__global__ void k_zero() {
    int i = blockIdx.x*blockDim.x + threadIdx.x;
    if (i <= NN) g_off[i] = 0;
    if (i < 3*HIDC) { g_cs1[i] = 0.f; g_cs2[i] = 0.f; }
}

__global__ void k_hist(const int* __restrict__ dst) {
    int e = blockIdx.x*blockDim.x + threadIdx.x;
    if (e < EE) atomicAdd(&g_off[dst[e]], 1);
}

__global__ void k_scan1() {
    __shared__ int s[1024];
    int t = threadIdx.x;
    int i = blockIdx.x*1024 + t;
    int v = (i < NN) ? g_off[i] : 0;
    s[t] = v;
    __syncthreads();
    for (int o = 1; o < 1024; o <<= 1) {
        int x = (t >= o) ? s[t-o] : 0;
        __syncthreads();
        s[t] += x;
        __syncthreads();
    }
    int incl = s[t];
    if (i < NN) g_off[i] = incl - v;     // exclusive within block
    if (t == 1023) g_bsum[blockIdx.x] = incl;
}

// scan2 + scan3 fused: each 256-block lies inside one 1024-chunk
__global__ void k_scan23() {
    __shared__ int base;
    int t = threadIdx.x;
    if (t == 0) {
        int cid = (blockIdx.x * 256) >> 10;
        int s = 0;
        for (int b = 0; b < cid; ++b) s += g_bsum[b];
        base = s;
    }
    __syncthreads();
    int i = blockIdx.x*256 + t;
    if (i < NN) {
        int o = g_off[i] + base;
        g_off[i] = o;
        g_cur[i] = o;
    }
    if (i == 0) g_off[NN] = EE;
}

__global__ void k_fill(const int* __restrict__ src, const int* __restrict__ dst) {
    int e = blockIdx.x*blockDim.x + threadIdx.x;
    if (e < EE) {
        int d = dst[e];
        int p = atomicAdd(&g_cur[d], 1);
        g_eid[p] = src[e];
    }
}

__global__ void k_gstart(const int* __restrict__ batch) {
    int g = threadIdx.x;
    if (g > GG) return;
    if (g == GG) { g_gs[GG] = NN; return; }
    int lo = 0, hi = NN;
    while (lo < hi) { int mid = (lo + hi) >> 1; if (batch[mid] < g) lo = mid + 1; else hi = mid; }
    g_gs[g] = lo;
}

// ---------------- tensor-core GEMM: out = A @ W^T + b ------------------------
// bf16 split (hi + residual), 3 MMAs per tile: AhBh + AhBl + AlBh  (~2^-16 rel err)
// block tile: 64 rows x 128 cols, K=128. gridDim.y: 0 -> (Wl, bl, g_hl); 1 -> (Wr, br, g_m)
// 8 warps = 2 (m32) x 4 (n32). warp: m32 x n32 -> 2x4 m16n8k16 tiles.
// smem rows padded to 68 words (68 mod 32 == 4 -> fragment LDS conflict-free: 4g+tg).

#define SA_W 68
#define GEMM_SMEM_WORDS (2*64*SA_W + 2*128*SA_W)
#define GEMM_SMEM_BYTES (GEMM_SMEM_WORDS*4)

__device__ __forceinline__ void cvt_hilo(float x, float y, unsigned& hi, unsigned& lo) {
    __nv_bfloat162 h = __floats2bfloat162_rn(x, y);   // .x=x (low half), .y=y (high half)
    float rx = x - __low2float(h);
    float ry = y - __high2float(h);
    __nv_bfloat162 l = __floats2bfloat162_rn(rx, ry);
    hi = *reinterpret_cast<unsigned*>(&h);
    lo = *reinterpret_cast<unsigned*>(&l);
}

__device__ __forceinline__ void mma16816(float* d, const unsigned* a, const unsigned* b) {
    asm volatile("mma.sync.aligned.m16n8k16.row.col.f32.bf16.bf16.f32 "
        "{%0,%1,%2,%3}, {%4,%5,%6,%7}, {%8,%9}, {%0,%1,%2,%3};"
        : "+f"(d[0]), "+f"(d[1]), "+f"(d[2]), "+f"(d[3])
        : "r"(a[0]), "r"(a[1]), "r"(a[2]), "r"(a[3]), "r"(b[0]), "r"(b[1]));
}

__global__ __launch_bounds__(256, 2) void k_gemm_tc(
    const float* __restrict__ Ain,
    const float* __restrict__ Wl, const float* __restrict__ Wr,
    const float* __restrict__ bl, const float* __restrict__ br)
{
    extern __shared__ unsigned sm[];
    unsigned* Ah = sm;                       // [64][68]
    unsigned* Al = sm + 64*SA_W;             // [64][68]
    unsigned* Wh = sm + 2*64*SA_W;           // [128][68]
    unsigned* Wo = sm + 2*64*SA_W + 128*SA_W;// [128][68]

    const float* A    = Ain ? Ain : g_h;
    const float* W    = blockIdx.y ? Wr : Wl;
    const float* bias = blockIdx.y ? br : bl;
    float*       out  = blockIdx.y ? g_m : g_hl;

    int tid = threadIdx.x;
    int r0  = blockIdx.x * 64;

    // load + split W (128x128 f32 -> bf16 hi/lo)
    #pragma unroll
    for (int it = 0; it < 16; ++it) {
        int idx = it*256 + tid;            // 0..4095 float4s
        int n  = idx >> 5;
        int kq = idx & 31;
        float4 v = *(const float4*)(W + n*128 + kq*4);
        unsigned h0,l0,h1,l1;
        cvt_hilo(v.x, v.y, h0, l0);
        cvt_hilo(v.z, v.w, h1, l1);
        Wh[n*SA_W + 2*kq]   = h0;  Wh[n*SA_W + 2*kq+1] = h1;
        Wo[n*SA_W + 2*kq]   = l0;  Wo[n*SA_W + 2*kq+1] = l1;
    }
    // load + split A tile (64x128)
    #pragma unroll
    for (int it = 0; it < 8; ++it) {
        int idx = it*256 + tid;            // 0..2047 float4s
        int rl = idx >> 5;
        int kq = idx & 31;
        float4 v = make_float4(0.f,0.f,0.f,0.f);
        if (r0 + rl < NN) v = *(const float4*)(A + (r0+rl)*128 + kq*4);
        unsigned h0,l0,h1,l1;
        cvt_hilo(v.x, v.y, h0, l0);
        cvt_hilo(v.z, v.w, h1, l1);
        Ah[rl*SA_W + 2*kq]   = h0;  Ah[rl*SA_W + 2*kq+1] = h1;
        Al[rl*SA_W + 2*kq]   = l0;  Al[rl*SA_W + 2*kq+1] = l1;
    }

    int lane = tid & 31, g = lane >> 2, tg = lane & 3;
    int wid = tid >> 5, mw = wid & 1, nw = wid >> 1;

    float acc[2][4][4];
    #pragma unroll
    for (int nn = 0; nn < 4; ++nn) {
        int col = nw*32 + nn*8 + 2*tg;
        float b0 = bias[col], b1 = bias[col+1];
        #pragma unroll
        for (int mm = 0; mm < 2; ++mm) {
            acc[mm][nn][0] = b0; acc[mm][nn][1] = b1;
            acc[mm][nn][2] = b0; acc[mm][nn][3] = b1;
        }
    }
    __syncthreads();

    #pragma unroll
    for (int kc = 0; kc < 8; ++kc) {
        int w0 = tg + kc*8;
        unsigned ah[2][4], al[2][4];
        #pragma unroll
        for (int mm = 0; mm < 2; ++mm) {
            int rb = mw*32 + mm*16;
            ah[mm][0] = Ah[(rb+g  )*SA_W + w0];
            ah[mm][1] = Ah[(rb+g+8)*SA_W + w0];
            ah[mm][2] = Ah[(rb+g  )*SA_W + w0+4];
            ah[mm][3] = Ah[(rb+g+8)*SA_W + w0+4];
            al[mm][0] = Al[(rb+g  )*SA_W + w0];
            al[mm][1] = Al[(rb+g+8)*SA_W + w0];
            al[mm][2] = Al[(rb+g  )*SA_W + w0+4];
            al[mm][3] = Al[(rb+g+8)*SA_W + w0+4];
        }
        unsigned bh[4][2], blo[4][2];
        #pragma unroll
        for (int nn = 0; nn < 4; ++nn) {
            int n = nw*32 + nn*8 + g;
            bh [nn][0] = Wh[n*SA_W + w0];  bh [nn][1] = Wh[n*SA_W + w0+4];
            blo[nn][0] = Wo[n*SA_W + w0];  blo[nn][1] = Wo[n*SA_W + w0+4];
        }
        #pragma unroll
        for (int mm = 0; mm < 2; ++mm)
            #pragma unroll
            for (int nn = 0; nn < 4; ++nn) {
                mma16816(acc[mm][nn], ah[mm], bh[nn]);
                mma16816(acc[mm][nn], ah[mm], blo[nn]);
                mma16816(acc[mm][nn], al[mm], bh[nn]);
            }
    }

    #pragma unroll
    for (int mm = 0; mm < 2; ++mm)
        #pragma unroll
        for (int nn = 0; nn < 4; ++nn) {
            int row = r0 + mw*32 + mm*16 + g;
            int col = nw*32 + nn*8 + 2*tg;
            if (row < NN)
                *(float2*)(out + row*128 + col) = make_float2(acc[mm][nn][0], acc[mm][nn][1]);
            if (row + 8 < NN)
                *(float2*)(out + (row+8)*128 + col) = make_float2(acc[mm][nn][2], acc[mm][nn][3]);
        }
}

// ---------------- per-layer: gather-mean + combine + L2 norm + BN stats ------
__global__ void k_agg(int slot) {
    __shared__ float s1[128], s2[128];
    int tid = threadIdx.x;
    if (tid < 128) { s1[tid] = 0.f; s2[tid] = 0.f; }
    __syncthreads();
    int lane = tid & 31;
    int wid  = blockIdx.x*8 + (tid >> 5);
    int nw   = gridDim.x*8;
    float c1x=0,c1y=0,c1z=0,c1w=0, c2x=0,c2y=0,c2z=0,c2w=0;
    for (int node = wid; node < NN; node += nw) {
        int e0 = g_off[node], e1 = g_off[node+1];
        float ax=0, ay=0, az=0, aw=0;
        for (int e = e0; e < e1; ++e) {
            int srow = g_eid[e];
            float4 v = *(const float4*)(g_m + srow*128 + lane*4);
            ax += v.x; ay += v.y; az += v.z; aw += v.w;
        }
        float inv = 1.f / fmaxf((float)(e1 - e0), 1.f);
        float4 h = *(const float4*)(g_hl + node*128 + lane*4);
        h.x += ax*inv; h.y += ay*inv; h.z += az*inv; h.w += aw*inv;
        float ss = h.x*h.x + h.y*h.y + h.z*h.z + h.w*h.w;
        #pragma unroll
        for (int o = 16; o > 0; o >>= 1) ss += __shfl_xor_sync(0xffffffffu, ss, o);
        float sc = 1.f / fmaxf(sqrtf(ss), 1e-12f);
        h.x *= sc; h.y *= sc; h.z *= sc; h.w *= sc;
        *(float4*)(g_hl + node*128 + lane*4) = h;
        c1x += h.x; c1y += h.y; c1z += h.z; c1w += h.w;
        c2x += h.x*h.x; c2y += h.y*h.y; c2z += h.z*h.z; c2w += h.w*h.w;
    }
    atomicAdd(&s1[lane*4+0], c1x); atomicAdd(&s1[lane*4+1], c1y);
    atomicAdd(&s1[lane*4+2], c1z); atomicAdd(&s1[lane*4+3], c1w);
    atomicAdd(&s2[lane*4+0], c2x); atomicAdd(&s2[lane*4+1], c2y);
    atomicAdd(&s2[lane*4+2], c2z); atomicAdd(&s2[lane*4+3], c2w);
    __syncthreads();
    if (tid < 128) {
        atomicAdd(&g_cs1[slot*128 + tid], s1[tid]);
        atomicAdd(&g_cs2[slot*128 + tid], s2[tid]);
    }
}

__global__ void k_bn_apply(const float* __restrict__ gamma, const float* __restrict__ beta,
                           int slot) {
    __shared__ float smu[128], srs[128];
    int tid = threadIdx.x;
    if (tid < 128) {
        const float invn = 1.f / (float)NN;
        float mu  = g_cs1[slot*128 + tid] * invn;
        float var = g_cs2[slot*128 + tid] * invn - mu*mu;
        smu[tid] = mu;
        srs[tid] = rsqrtf(var + 1e-5f);
    }
    __syncthreads();
    int i = blockIdx.x*blockDim.x + tid;
    const int tot = NN*32;           // float4 count
    for (; i < tot; i += gridDim.x*blockDim.x) {
        int c = (i & 31) * 4;
        float4 v = *(const float4*)(g_hl + (size_t)i*4);
        v.x = fmaxf(gamma[c+0]*(v.x - smu[c+0])*srs[c+0] + beta[c+0], 0.f);
        v.y = fmaxf(gamma[c+1]*(v.y - smu[c+1])*srs[c+1] + beta[c+1], 0.f);
        v.z = fmaxf(gamma[c+2]*(v.z - smu[c+2])*srs[c+2] + beta[c+2], 0.f);
        v.w = fmaxf(gamma[c+3]*(v.w - smu[c+3])*srs[c+3] + beta[c+3], 0.f);
        *(float4*)(g_h + (size_t)i*4) = v;
    }
}

// ---------------- pooling + head ---------------------------------------------
__global__ void k_pool() {
    int g = blockIdx.x, t = threadIdx.x;
    int s = g_gs[g], e = g_gs[g+1];
    float acc = 0.f;
    int node = s;
    for (; node + 16 <= e; node += 16) {
        float p = 0.f;
        #pragma unroll
        for (int j = 0; j < 16; ++j) p += g_h[(node+j)*128 + t];
        acc += p;
    }
    for (; node < e; ++node) acc += g_h[node*128 + t];
    g_pool[g*128 + t] = acc;
}

__global__ void k_head(const float* __restrict__ W1, const float* __restrict__ b1,
                       const float* __restrict__ W2, const float* __restrict__ b2,
                       float* __restrict__ out)
{
    __shared__ float ps[128], us[128], ls[OUTC], st[2];
    int g = blockIdx.x, t = threadIdx.x;
    float cg = (float)(g_gs[g+1] - g_gs[g]);
    ps[t] = g_pool[g*128 + t];
    __syncthreads();
    float u = b1[t] * cg;
    #pragma unroll 8
    for (int k = 0; k < 128; ++k) u += ps[k] * W1[t*128 + k];
    us[t] = u;
    __syncthreads();
    if (t < OUTC) {
        float l = b2[t] * cg;
        #pragma unroll 8
        for (int k = 0; k < 128; ++k) l += us[k] * W2[t*128 + k];
        ls[t] = l;
    }
    __syncthreads();
    if (t == 0) {
        float mx = -1e30f;
        for (int j = 0; j < OUTC; ++j) mx = fmaxf(mx, ls[j]);
        float se = 0.f;
        for (int j = 0; j < OUTC; ++j) se += expf(ls[j] - mx);
        st[0] = mx; st[1] = logf(se);
    }
    __syncthreads();
    if (t < OUTC) out[g*OUTC + t] = ls[t] - st[0] - st[1];
}

// ---------------- launch ------------------------------------------------------
extern "C" void kernel_launch(void* const* d_in, const int* in_sizes, int n_in,
                              void* d_out, int out_size)
{
    const float* x     = (const float*)d_in[0];
    const int*   ei    = (const int*)  d_in[1];
    const int*   batch = (const int*)  d_in[2];
    const float* Wl    = (const float*)d_in[3];
    const float* bl    = (const float*)d_in[4];
    const float* Wr    = (const float*)d_in[5];
    const float* br    = (const float*)d_in[6];
    const float* gamma = (const float*)d_in[7];
    const float* beta  = (const float*)d_in[8];
    const float* W1    = (const float*)d_in[9];
    const float* b1    = (const float*)d_in[10];
    const float* W2    = (const float*)d_in[11];
    const float* b2    = (const float*)d_in[12];
    float* out = (float*)d_out;

    const int* src = ei;
    const int* dst = ei + EE;

    cudaFuncSetAttribute(k_gemm_tc, cudaFuncAttributeMaxDynamicSharedMemorySize,
                         GEMM_SMEM_BYTES);

    dim3 ggrid((NN + 63) / 64, 2, 1);

    // CSR by dst (rebuilt every call; deterministic work)
    k_zero  <<<391, 256>>>();                 // launch 0
    k_hist  <<<2344, 256>>>(dst);             // 1
    k_scan1 <<<NB_SCAN, 1024>>>();            // 2
    k_scan23<<<391, 256>>>();                 // 3
    k_fill  <<<2344, 256>>>(src, dst);        // 4

    for (int i = 0; i < 3; ++i) {
        const float* Ain = (i == 0) ? x : nullptr;   // nullptr -> read g_h
        k_gemm_tc<<<ggrid, 256, GEMM_SMEM_BYTES>>>(   // launch 5 on i==0 -> ncu target
            Ain, Wl + i*HIDC*HIDC, Wr + i*HIDC*HIDC, bl + i*HIDC, br + i*HIDC);
        if (i == 0) k_gstart<<<1, GG+1>>>(batch);
        k_agg<<<1480, 256>>>(i);
        k_bn_apply<<<2048, 256>>>(gamma + i*HIDC, beta + i*HIDC, i);
    }

    k_pool<<<GG, 128>>>();
    k_head<<<GG, 128>>>(W1, b1, W2, b2, out);
}

// round 10
// speedup vs baseline: 1.8875x; 1.1791x over previous
#include <cuda_runtime.h>
#include <cuda_bf16.h>
#include <cuda_fp16.h>

#define NN   100000
#define EE   600000
#define HIDC 128
#define OUTC 40
#define GG   64
#define NB_SCAN 98           // ceil(100000/1024)
#define NT   1563            // ceil(100000/64) row tiles

// ---------------- persistent scratch (static device arrays; no allocation) ----
__device__ __half2 g_m2[NN*64];   // lin_r output (messages), fp16
__device__ float   g_hl[NN*HIDC]; // lin_l output, then normalized h2
__device__ int   g_off[NN+1];     // CSR offsets by dst
__device__ int   g_cur[NN];       // fill cursors
__device__ int   g_eid[EE];       // CSR src ids
__device__ int   g_bsum[NB_SCAN];
__device__ float g_cs1[3*HIDC];   // per-layer BN column sums
__device__ float g_cs2[3*HIDC];
__device__ float g_pool[GG*HIDC];
__device__ int   g_gs[GG+1];      // per-graph node range (batch is sorted)
__device__ int   g_ctr[4];        // GEMM tile work-steal counters (per layer)

// ---------------- init --------------------------------------------------------
__global__ void k_zero() {
    int i = blockIdx.x*blockDim.x + threadIdx.x;
    if (i <= NN) g_off[i] = 0;
    if (i < 3*HIDC) { g_cs1[i] = 0.f; g_cs2[i] = 0.f; }
    if (i < 4) g_ctr[i] = 0;
}

__global__ void k_hist(const int* __restrict__ dst) {
    int e = blockIdx.x*blockDim.x + threadIdx.x;
    if (e < EE) atomicAdd(&g_off[dst[e]], 1);
}

__global__ void k_scan1() {
    __shared__ int s[1024];
    int t = threadIdx.x;
    int i = blockIdx.x*1024 + t;
    int v = (i < NN) ? g_off[i] : 0;
    s[t] = v;
    __syncthreads();
    for (int o = 1; o < 1024; o <<= 1) {
        int x = (t >= o) ? s[t-o] : 0;
        __syncthreads();
        s[t] += x;
        __syncthreads();
    }
    int incl = s[t];
    if (i < NN) g_off[i] = incl - v;     // exclusive within chunk
    if (t == 1023) g_bsum[blockIdx.x] = incl;
}

// parallel exclusive scan of the 98 chunk sums, in place
__global__ void k_scan2p() {
    __shared__ int s[128];
    int t = threadIdx.x;
    int v = (t < NB_SCAN) ? g_bsum[t] : 0;
    s[t] = v;
    __syncthreads();
    for (int o = 1; o < 128; o <<= 1) {
        int x = (t >= o) ? s[t-o] : 0;
        __syncthreads();
        s[t] += x;
        __syncthreads();
    }
    if (t < NB_SCAN) g_bsum[t] = s[t] - v;   // exclusive prefix
}

__global__ void k_scan3() {
    int i = blockIdx.x*blockDim.x + threadIdx.x;
    if (i < NN) {
        int o = g_off[i] + g_bsum[i >> 10];
        g_off[i] = o;
        g_cur[i] = o;
    }
    if (i == 0) g_off[NN] = EE;
}

__global__ void k_fill(const int* __restrict__ src, const int* __restrict__ dst) {
    int e = blockIdx.x*blockDim.x + threadIdx.x;
    if (e < EE) {
        int d = dst[e];
        int p = atomicAdd(&g_cur[d], 1);
        g_eid[p] = src[e];
    }
}

__global__ void k_gstart(const int* __restrict__ batch) {
    int g = threadIdx.x;
    if (g > GG) return;
    if (g == GG) { g_gs[GG] = NN; return; }
    int lo = 0, hi = NN;
    while (lo < hi) { int mid = (lo + hi) >> 1; if (batch[mid] < g) lo = mid + 1; else hi = mid; }
    g_gs[g] = lo;
}

// ---------------- persistent tensor-core GEMM --------------------------------
// out_l = BNReLU(A) @ Wl^T + bl -> g_hl ;  out_r = ... @ Wr^T + br -> g_m2 (fp16)
// bf16 split (hi + residual), 3 MMAs/tile. W (both mats, hi+lo) in smem once
// per CTA; A tiles double-buffered, work-stealing over NT tiles.
// 256 threads = 8 warps: 2 (m32) x 4 (n64). smem row stride 68 words.

#define SA_W 68
#define GEMM_SMEM_WORDS (2*256*SA_W + 4*64*SA_W)
#define GEMM_SMEM_BYTES (GEMM_SMEM_WORDS*4)

__device__ __forceinline__ void cvt_hilo(float x, float y, unsigned& hi, unsigned& lo) {
    __nv_bfloat162 h = __floats2bfloat162_rn(x, y);
    float rx = x - __low2float(h);
    float ry = y - __high2float(h);
    __nv_bfloat162 l = __floats2bfloat162_rn(rx, ry);
    hi = *reinterpret_cast<unsigned*>(&h);
    lo = *reinterpret_cast<unsigned*>(&l);
}

__device__ __forceinline__ void mma16816(float* d, const unsigned* a, const unsigned* b) {
    asm volatile("mma.sync.aligned.m16n8k16.row.col.f32.bf16.bf16.f32 "
        "{%0,%1,%2,%3}, {%4,%5,%6,%7}, {%8,%9}, {%0,%1,%2,%3};"
        : "+f"(d[0]), "+f"(d[1]), "+f"(d[2]), "+f"(d[3])
        : "r"(a[0]), "r"(a[1]), "r"(a[2]), "r"(a[3]), "r"(b[0]), "r"(b[1]));
}

__global__ __launch_bounds__(256, 1) void k_gemm_tc(
    const float* __restrict__ Ain,       // null -> g_hl
    const float* __restrict__ Wl, const float* __restrict__ Wr,
    const float* __restrict__ bl, const float* __restrict__ br,
    const float* __restrict__ gamma, const float* __restrict__ beta,
    int bnslot, int layer)
{
    extern __shared__ unsigned sm[];
    unsigned* Wh = sm;                     // [256][68]
    unsigned* Wo = sm + 256*SA_W;          // [256][68]
    unsigned* Ab = sm + 2*256*SA_W;        // 2 bufs x (Ah[64][68] ++ Al[64][68])
    __shared__ int s_t[2];

    const float* A = Ain ? Ain : g_hl;
    int tid = threadIdx.x;

    // ---- load + split both W matrices (once per CTA) ----
    #pragma unroll
    for (int it = 0; it < 32; ++it) {
        int idx = it*256 + tid;
        int n = idx >> 5, wq = idx & 31;
        const float* Wsrc = (n < 128) ? (Wl + n*128 + wq*4) : (Wr + (n-128)*128 + wq*4);
        float4 v = *(const float4*)Wsrc;
        unsigned h0,l0,h1,l1;
        cvt_hilo(v.x, v.y, h0, l0);
        cvt_hilo(v.z, v.w, h1, l1);
        Wh[n*SA_W + 2*wq] = h0;  Wh[n*SA_W + 2*wq+1] = h1;
        Wo[n*SA_W + 2*wq] = l0;  Wo[n*SA_W + 2*wq+1] = l1;
    }

    // ---- BN+ReLU coefficients for this thread's fixed 4 A-columns ----
    int kq = tid & 31, rbase = tid >> 5;
    float ca[4], cb[4];
    if (bnslot >= 0) {
        const float invn = 1.f / (float)NN;
        #pragma unroll
        for (int j = 0; j < 4; ++j) {
            int c = 4*kq + j;
            float mu  = g_cs1[bnslot*128 + c] * invn;
            float var = g_cs2[bnslot*128 + c] * invn - mu*mu;
            float aa  = gamma[c] * rsqrtf(var + 1e-5f);
            ca[j] = aa;
            cb[j] = beta[c] - mu*aa;
        }
    }

    int lane = tid & 31, g = lane >> 2, tg = lane & 3;
    int wid = tid >> 5, mw = wid & 1, nw = wid >> 1;

    // per-warp bias registers (col layout fixed across tiles)
    float2 bias[8];
    #pragma unroll
    for (int nn = 0; nn < 8; ++nn) {
        int col = nw*64 + nn*8 + 2*tg;
        const float* bsrc = (col < 128) ? bl : br;
        bias[nn] = make_float2(bsrc[col & 127], bsrc[(col & 127) + 1]);
    }

    // ---- steal first tile, prefetch + split into buf0 ----
    if (tid == 0) s_t[0] = atomicAdd(&g_ctr[layer], 1);
    __syncthreads();
    int t = s_t[0];
    int cur = 0;
    bool have = (t < NT);

    float4 pf[8];
    if (have) {
        #pragma unroll
        for (int it = 0; it < 8; ++it) {
            int row = t*64 + it*8 + rbase;
            pf[it] = (row < NN) ? *(const float4*)(A + (size_t)row*128 + kq*4)
                                : make_float4(0.f,0.f,0.f,0.f);
        }
        unsigned* Ah = Ab;           // buf0
        unsigned* Al = Ab + 64*SA_W;
        #pragma unroll
        for (int it = 0; it < 8; ++it) {
            int rl = it*8 + rbase;
            float4 v = pf[it];
            if (bnslot >= 0) {
                v.x = fmaxf(ca[0]*v.x + cb[0], 0.f);
                v.y = fmaxf(ca[1]*v.y + cb[1], 0.f);
                v.z = fmaxf(ca[2]*v.z + cb[2], 0.f);
                v.w = fmaxf(ca[3]*v.w + cb[3], 0.f);
            }
            unsigned h0,l0,h1,l1;
            cvt_hilo(v.x, v.y, h0, l0);
            cvt_hilo(v.z, v.w, h1, l1);
            Ah[rl*SA_W + 2*kq] = h0;  Ah[rl*SA_W + 2*kq+1] = h1;
            Al[rl*SA_W + 2*kq] = l0;  Al[rl*SA_W + 2*kq+1] = l1;
        }
    }

    while (have) {
        if (tid == 0) s_t[cur^1] = atomicAdd(&g_ctr[layer], 1);
        __syncthreads();                       // buf(cur) + s_t visible
        int tn = s_t[cur^1];
        bool nhave = (tn < NT);

        // prefetch next A tile (global loads overlap the MMAs below)
        if (nhave) {
            #pragma unroll
            for (int it = 0; it < 8; ++it) {
                int row = tn*64 + it*8 + rbase;
                pf[it] = (row < NN) ? *(const float4*)(A + (size_t)row*128 + kq*4)
                                    : make_float4(0.f,0.f,0.f,0.f);
            }
        }

        // ---- MMA on buf(cur) ----
        unsigned* Ah = Ab + cur*(2*64*SA_W);
        unsigned* Al = Ah + 64*SA_W;
        int r0 = t*64;

        float acc[2][8][4];
        #pragma unroll
        for (int mm = 0; mm < 2; ++mm)
            #pragma unroll
            for (int nn = 0; nn < 8; ++nn) {
                acc[mm][nn][0] = bias[nn].x; acc[mm][nn][1] = bias[nn].y;
                acc[mm][nn][2] = bias[nn].x; acc[mm][nn][3] = bias[nn].y;
            }

        #pragma unroll
        for (int kc = 0; kc < 8; ++kc) {
            int w0 = tg + kc*8;
            unsigned ah[2][4], al[2][4];
            #pragma unroll
            for (int mm = 0; mm < 2; ++mm) {
                int rb = mw*32 + mm*16;
                ah[mm][0] = Ah[(rb+g  )*SA_W + w0];
                ah[mm][1] = Ah[(rb+g+8)*SA_W + w0];
                ah[mm][2] = Ah[(rb+g  )*SA_W + w0+4];
                ah[mm][3] = Ah[(rb+g+8)*SA_W + w0+4];
                al[mm][0] = Al[(rb+g  )*SA_W + w0];
                al[mm][1] = Al[(rb+g+8)*SA_W + w0];
                al[mm][2] = Al[(rb+g  )*SA_W + w0+4];
                al[mm][3] = Al[(rb+g+8)*SA_W + w0+4];
            }
            unsigned bh[8][2], blo[8][2];
            #pragma unroll
            for (int nn = 0; nn < 8; ++nn) {
                int n = nw*64 + nn*8 + g;
                bh [nn][0] = Wh[n*SA_W + w0];  bh [nn][1] = Wh[n*SA_W + w0+4];
                blo[nn][0] = Wo[n*SA_W + w0];  blo[nn][1] = Wo[n*SA_W + w0+4];
            }
            // grouped by term: 16 independent MMAs between same-acc reuses
            #pragma unroll
            for (int mm = 0; mm < 2; ++mm)
                #pragma unroll
                for (int nn = 0; nn < 8; ++nn) mma16816(acc[mm][nn], ah[mm], bh[nn]);
            #pragma unroll
            for (int mm = 0; mm < 2; ++mm)
                #pragma unroll
                for (int nn = 0; nn < 8; ++nn) mma16816(acc[mm][nn], ah[mm], blo[nn]);
            #pragma unroll
            for (int mm = 0; mm < 2; ++mm)
                #pragma unroll
                for (int nn = 0; nn < 8; ++nn) mma16816(acc[mm][nn], al[mm], bh[nn]);
        }

        // ---- epilogue: cols<128 -> g_hl fp32, cols>=128 -> g_m2 fp16 ----
        #pragma unroll
        for (int mm = 0; mm < 2; ++mm) {
            int row = r0 + mw*32 + mm*16 + g;
            #pragma unroll
            for (int nn = 0; nn < 8; ++nn) {
                int col = nw*64 + nn*8 + 2*tg;
                if (col < 128) {
                    if (row < NN)
                        *(float2*)(g_hl + (size_t)row*128 + col) =
                            make_float2(acc[mm][nn][0], acc[mm][nn][1]);
                    if (row + 8 < NN)
                        *(float2*)(g_hl + (size_t)(row+8)*128 + col) =
                            make_float2(acc[mm][nn][2], acc[mm][nn][3]);
                } else {
                    int mc = (col - 128) >> 1;
                    if (row < NN)
                        g_m2[(size_t)row*64 + mc] =
                            __floats2half2_rn(acc[mm][nn][0], acc[mm][nn][1]);
                    if (row + 8 < NN)
                        g_m2[(size_t)(row+8)*64 + mc] =
                            __floats2half2_rn(acc[mm][nn][2], acc[mm][nn][3]);
                }
            }
        }

        // ---- split prefetched A into the other buffer ----
        if (nhave) {
            unsigned* nAh = Ab + (cur^1)*(2*64*SA_W);
            unsigned* nAl = nAh + 64*SA_W;
            #pragma unroll
            for (int it = 0; it < 8; ++it) {
                int rl = it*8 + rbase;
                float4 v = pf[it];
                if (bnslot >= 0) {
                    v.x = fmaxf(ca[0]*v.x + cb[0], 0.f);
                    v.y = fmaxf(ca[1]*v.y + cb[1], 0.f);
                    v.z = fmaxf(ca[2]*v.z + cb[2], 0.f);
                    v.w = fmaxf(ca[3]*v.w + cb[3], 0.f);
                }
                unsigned h0,l0,h1,l1;
                cvt_hilo(v.x, v.y, h0, l0);
                cvt_hilo(v.z, v.w, h1, l1);
                nAh[rl*SA_W + 2*kq] = h0;  nAh[rl*SA_W + 2*kq+1] = h1;
                nAl[rl*SA_W + 2*kq] = l0;  nAl[rl*SA_W + 2*kq+1] = l1;
            }
        }
        t = tn; cur ^= 1; have = nhave;
    }
}

// ---------------- gather-mean + combine + L2 norm + BN stats -----------------
__global__ void k_agg(int slot) {
    __shared__ float s1[128], s2[128];
    int tid = threadIdx.x;
    if (tid < 128) { s1[tid] = 0.f; s2[tid] = 0.f; }
    __syncthreads();
    int lane = tid & 31;
    int wid  = blockIdx.x*8 + (tid >> 5);
    int nw   = gridDim.x*8;
    float c1x=0,c1y=0,c1z=0,c1w=0, c2x=0,c2y=0,c2z=0,c2w=0;
    for (int node = wid; node < NN; node += nw) {
        int e0 = g_off[node], e1 = g_off[node+1];
        float ax=0, ay=0, az=0, aw=0;
        for (int e = e0; e < e1; ++e) {
            int srow = g_eid[e];
            uint2 raw = *(const uint2*)(g_m2 + (size_t)srow*64 + lane*2);
            float2 f0 = __half22float2(*reinterpret_cast<__half2*>(&raw.x));
            float2 f1 = __half22float2(*reinterpret_cast<__half2*>(&raw.y));
            ax += f0.x; ay += f0.y; az += f1.x; aw += f1.y;
        }
        float inv = 1.f / fmaxf((float)(e1 - e0), 1.f);
        float4 h = *(const float4*)(g_hl + (size_t)node*128 + lane*4);
        h.x += ax*inv; h.y += ay*inv; h.z += az*inv; h.w += aw*inv;
        float ss = h.x*h.x + h.y*h.y + h.z*h.z + h.w*h.w;
        #pragma unroll
        for (int o = 16; o > 0; o >>= 1) ss += __shfl_xor_sync(0xffffffffu, ss, o);
        float sc = 1.f / fmaxf(sqrtf(ss), 1e-12f);
        h.x *= sc; h.y *= sc; h.z *= sc; h.w *= sc;
        *(float4*)(g_hl + (size_t)node*128 + lane*4) = h;
        c1x += h.x; c1y += h.y; c1z += h.z; c1w += h.w;
        c2x += h.x*h.x; c2y += h.y*h.y; c2z += h.z*h.z; c2w += h.w*h.w;
    }
    atomicAdd(&s1[lane*4+0], c1x); atomicAdd(&s1[lane*4+1], c1y);
    atomicAdd(&s1[lane*4+2], c1z); atomicAdd(&s1[lane*4+3], c1w);
    atomicAdd(&s2[lane*4+0], c2x); atomicAdd(&s2[lane*4+1], c2y);
    atomicAdd(&s2[lane*4+2], c2z); atomicAdd(&s2[lane*4+3], c2w);
    __syncthreads();
    if (tid < 128) {
        atomicAdd(&g_cs1[slot*128 + tid], s1[tid]);
        atomicAdd(&g_cs2[slot*128 + tid], s2[tid]);
    }
}

// ---------------- pooling (BN+ReLU of last layer fused) + head ---------------
__global__ void k_pool(const float* __restrict__ gamma, const float* __restrict__ beta) {
    int g = blockIdx.x, t = threadIdx.x;
    const float invn = 1.f / (float)NN;
    float mu  = g_cs1[2*128 + t] * invn;
    float var = g_cs2[2*128 + t] * invn - mu*mu;
    float a   = gamma[t] * rsqrtf(var + 1e-5f);
    float b   = beta[t] - mu*a;
    int s = g_gs[g], e = g_gs[g+1];
    float acc = 0.f;
    for (int node = s; node < e; ++node)
        acc += fmaxf(a * g_hl[(size_t)node*128 + t] + b, 0.f);
    g_pool[g*128 + t] = acc;
}

__global__ void k_head(const float* __restrict__ W1, const float* __restrict__ b1,
                       const float* __restrict__ W2, const float* __restrict__ b2,
                       float* __restrict__ out)
{
    __shared__ float ps[128], us[128], ls[OUTC], st[2];
    int g = blockIdx.x, t = threadIdx.x;
    float cg = (float)(g_gs[g+1] - g_gs[g]);
    ps[t] = g_pool[g*128 + t];
    __syncthreads();
    float u = b1[t] * cg;
    #pragma unroll 8
    for (int k = 0; k < 128; ++k) u += ps[k] * W1[t*128 + k];
    us[t] = u;
    __syncthreads();
    if (t < OUTC) {
        float l = b2[t] * cg;
        #pragma unroll 8
        for (int k = 0; k < 128; ++k) l += us[k] * W2[t*128 + k];
        ls[t] = l;
    }
    __syncthreads();
    if (t == 0) {
        float mx = -1e30f;
        for (int j = 0; j < OUTC; ++j) mx = fmaxf(mx, ls[j]);
        float se = 0.f;
        for (int j = 0; j < OUTC; ++j) se += expf(ls[j] - mx);
        st[0] = mx; st[1] = logf(se);
    }
    __syncthreads();
    if (t < OUTC) out[g*OUTC + t] = ls[t] - st[0] - st[1];
}

// ---------------- launch ------------------------------------------------------
extern "C" void kernel_launch(void* const* d_in, const int* in_sizes, int n_in,
                              void* d_out, int out_size)
{
    const float* x     = (const float*)d_in[0];
    const int*   ei    = (const int*)  d_in[1];
    const int*   batch = (const int*)  d_in[2];
    const float* Wl    = (const float*)d_in[3];
    const float* bl    = (const float*)d_in[4];
    const float* Wr    = (const float*)d_in[5];
    const float* br    = (const float*)d_in[6];
    const float* gamma = (const float*)d_in[7];
    const float* beta  = (const float*)d_in[8];
    const float* W1    = (const float*)d_in[9];
    const float* b1    = (const float*)d_in[10];
    const float* W2    = (const float*)d_in[11];
    const float* b2    = (const float*)d_in[12];
    float* out = (float*)d_out;

    const int* src = ei;
    const int* dst = ei + EE;

    cudaFuncSetAttribute(k_gemm_tc, cudaFuncAttributeMaxDynamicSharedMemorySize,
                         GEMM_SMEM_BYTES);

    // CSR build interleaved so the GEMM sits at our launch index 3 (ncu target)
    k_zero   <<<391, 256>>>();                 // 0
    k_hist   <<<2344, 256>>>(dst);             // 1
    k_scan1  <<<NB_SCAN, 1024>>>();            // 2
    k_gemm_tc<<<152, 256, GEMM_SMEM_BYTES>>>(  // 3  <- profiled (layer 0, no BN)
        x, Wl, Wr, bl, br, gamma, beta, -1, 0);
    k_scan2p <<<1, 128>>>();                   // 4
    k_scan3  <<<391, 256>>>();                 // 5
    k_fill   <<<2344, 256>>>(src, dst);        // 6
    k_gstart <<<1, GG+1>>>(batch);             // 7

    k_agg<<<1480, 256>>>(0);                   // 8
    k_gemm_tc<<<152, 256, GEMM_SMEM_BYTES>>>(  // 9  (layer 1, BN slot 0 fused)
        nullptr, Wl + 1*HIDC*HIDC, Wr + 1*HIDC*HIDC, bl + 1*HIDC, br + 1*HIDC,
        gamma + 0*HIDC, beta + 0*HIDC, 0, 1);
    k_agg<<<1480, 256>>>(1);                   // 10
    k_gemm_tc<<<152, 256, GEMM_SMEM_BYTES>>>(  // 11 (layer 2, BN slot 1 fused)
        nullptr, Wl + 2*HIDC*HIDC, Wr + 2*HIDC*HIDC, bl + 2*HIDC, br + 2*HIDC,
        gamma + 1*HIDC, beta + 1*HIDC, 1, 2);
    k_agg<<<1480, 256>>>(2);                   // 12

    k_pool<<<GG, 128>>>(gamma + 2*HIDC, beta + 2*HIDC);  // 13 (BN slot 2 fused)
    k_head<<<GG, 128>>>(W1, b1, W2, b2, out);            // 14
}

// round 13
// speedup vs baseline: 2.4841x; 1.3161x over previous
#include <cuda_runtime.h>
#include <cuda_bf16.h>
#include <cuda_fp16.h>

#define NN   100000
#define EE   600000
#define HIDC 128
#define OUTC 40
#define GG   64
#define NB_SCAN 98           // ceil(100000/1024)
#define NTILE 1563           // ceil(100000/64) row tiles
#define GRID_G 152

// ---------------- persistent scratch ----------------------------------------
__device__ __half2 g_m2[NN*64];   // lin_r output (messages), fp16
__device__ float   g_hl[NN*HIDC]; // lin_l output, then normalized h2
__device__ int   g_off[NN+1];
__device__ int   g_cur[NN];
__device__ int   g_eid[EE];
__device__ int   g_bsum[NB_SCAN];
__device__ float g_cs1[3*HIDC];
__device__ float g_cs2[3*HIDC];
__device__ float g_pool[GG*HIDC];
__device__ int   g_gs[GG+1];

// ---------------- helpers -----------------------------------------------------
__device__ __forceinline__ unsigned s2u(const void* p) {
    unsigned a;
    asm("{ .reg .u64 t; cvta.to.shared.u64 t, %1; cvt.u32.u64 %0, t; }" : "=r"(a) : "l"(p));
    return a;
}
__device__ __forceinline__ void ldsm4(unsigned* r, unsigned addr) {
    asm volatile("ldmatrix.sync.aligned.m8n8.x4.shared.b16 {%0,%1,%2,%3}, [%4];"
        : "=r"(r[0]), "=r"(r[1]), "=r"(r[2]), "=r"(r[3]) : "r"(addr));
}
__device__ __forceinline__ void mma16816(float* d, const unsigned* a, const unsigned* b) {
    asm volatile("mma.sync.aligned.m16n8k16.row.col.f32.bf16.bf16.f32 "
        "{%0,%1,%2,%3}, {%4,%5,%6,%7}, {%8,%9}, {%0,%1,%2,%3};"
        : "+f"(d[0]), "+f"(d[1]), "+f"(d[2]), "+f"(d[3])
        : "r"(a[0]), "r"(a[1]), "r"(a[2]), "r"(a[3]), "r"(b[0]), "r"(b[1]));
}
__device__ __forceinline__ void cvt_hilo(float x, float y, unsigned& hi, unsigned& lo) {
    __nv_bfloat162 h = __floats2bfloat162_rn(x, y);
    float rx = x - __low2float(h);
    float ry = y - __high2float(h);
    __nv_bfloat162 l = __floats2bfloat162_rn(rx, ry);
    hi = *reinterpret_cast<unsigned*>(&h);
    lo = *reinterpret_cast<unsigned*>(&l);
}

// SMEM word layout (stride SA_W=68 words per row; 272B ≡ 16 mod 128 -> LDSM conflict-free)
#define SA_W 68
#define WB_WH   0                         // Wh [256][68]  (Wl hi rows 0-127, Wr hi rows 128-255)
#define WB_WO   (256*SA_W*4)              // Wo [128][68]  (Wl lo only)
#define WB_A    ((256+128)*SA_W*4)        // A: 2 bufs x (hi [64][68] ++ lo [64][68])
#define A_BUF_B (2*64*SA_W*4)             // 34816 bytes per buffer
#define A_LO_B  (64*SA_W*4)               // 17408
#define GEMM_SMEM_BYTES (WB_A + 2*A_BUF_B)   // 174080

// ---------------- CSR build / init -------------------------------------------
__global__ void k_zero() {
    int i = blockIdx.x*blockDim.x + threadIdx.x;
    if (i <= NN) g_off[i] = 0;
    if (i < 3*HIDC) { g_cs1[i] = 0.f; g_cs2[i] = 0.f; }
    if (i < GG*HIDC) g_pool[i] = 0.f;
}
__global__ void k_hist(const int* __restrict__ dst) {
    int e = blockIdx.x*blockDim.x + threadIdx.x;
    if (e < EE) atomicAdd(&g_off[dst[e]], 1);
}
__global__ void k_scan1() {
    __shared__ int s[1024];
    int t = threadIdx.x;
    int i = blockIdx.x*1024 + t;
    int v = (i < NN) ? g_off[i] : 0;
    s[t] = v;
    __syncthreads();
    for (int o = 1; o < 1024; o <<= 1) {
        int x = (t >= o) ? s[t-o] : 0;
        __syncthreads();
        s[t] += x;
        __syncthreads();
    }
    int incl = s[t];
    if (i < NN) g_off[i] = incl - v;
    if (t == 1023) g_bsum[blockIdx.x] = incl;
}
__global__ void k_scan2p() {
    __shared__ int s[128];
    int t = threadIdx.x;
    int v = (t < NB_SCAN) ? g_bsum[t] : 0;
    s[t] = v;
    __syncthreads();
    for (int o = 1; o < 128; o <<= 1) {
        int x = (t >= o) ? s[t-o] : 0;
        __syncthreads();
        s[t] += x;
        __syncthreads();
    }
    if (t < NB_SCAN) g_bsum[t] = s[t] - v;
}
__global__ void k_scan3() {
    int i = blockIdx.x*blockDim.x + threadIdx.x;
    if (i < NN) {
        int o = g_off[i] + g_bsum[i >> 10];
        g_off[i] = o;
        g_cur[i] = o;
    }
    if (i == 0) g_off[NN] = EE;
}
__global__ void k_fill(const int* __restrict__ src, const int* __restrict__ dst) {
    int e = blockIdx.x*blockDim.x + threadIdx.x;
    if (e < EE) {
        int d = dst[e];
        int p = atomicAdd(&g_cur[d], 1);
        g_eid[p] = src[e];
    }
}
__global__ void k_gstart(const int* __restrict__ batch) {
    int g = threadIdx.x;
    if (g > GG) return;
    if (g == GG) { g_gs[GG] = NN; return; }
    int lo = 0, hi = NN;
    while (lo < hi) { int mid = (lo + hi) >> 1; if (batch[mid] < g) lo = mid + 1; else hi = mid; }
    g_gs[g] = lo;
}

// ---------------- persistent tensor-core dual GEMM (mma.sync + ldmatrix) -----
// 64-row tile x 256 cols. 8 warps = 2(m32) x 4(n64). l-cols (0-127): 3 terms
// AhBh+AhBl+AlBh; r-cols (128-255): 2 terms (messages are fp16 anyway).
__global__ __launch_bounds__(256, 1) void k_gemm_tc(
    const float* __restrict__ Ain,       // null -> g_hl
    const float* __restrict__ Wl, const float* __restrict__ Wr,
    const float* __restrict__ bl, const float* __restrict__ br,
    const float* __restrict__ gamma, const float* __restrict__ beta,
    int bnslot)
{
    extern __shared__ __align__(16) unsigned sm[];
    unsigned* Wh = sm;                        // word pointers
    unsigned* Wo = sm + 256*SA_W;
    unsigned* Ab = sm + (256+128)*SA_W;
    const unsigned sb = s2u(sm);
    const float* A = Ain ? Ain : g_hl;
    int tid = threadIdx.x;

    // ---- load + split weights: Wl -> Wh(0-127)+Wo ; Wr -> Wh(128-255) hi only
    #pragma unroll
    for (int itr = 0; itr < 16; ++itr) {
        int idx = itr*256 + tid;              // 0..4095
        int n = idx >> 5, wq = idx & 31;
        float4 v = *(const float4*)(Wl + n*128 + wq*4);
        unsigned h0,l0,h1,l1;
        cvt_hilo(v.x, v.y, h0, l0);
        cvt_hilo(v.z, v.w, h1, l1);
        *(uint2*)(Wh + n*SA_W + 2*wq)       = make_uint2(h0, h1);
        *(uint2*)(Wo + n*SA_W + 2*wq)       = make_uint2(l0, l1);
        float4 w = *(const float4*)(Wr + n*128 + wq*4);
        cvt_hilo(w.x, w.y, h0, l0);
        cvt_hilo(w.z, w.w, h1, l1);
        *(uint2*)(Wh + (128+n)*SA_W + 2*wq) = make_uint2(h0, h1);
    }

    // ---- BN+ReLU coeffs for this thread's fixed 4 A-columns ----
    int kq = tid & 31, rbase = tid >> 5;      // A loader role
    float ca[4], cb[4];
    if (bnslot >= 0) {
        const float invn = 1.f / (float)NN;
        #pragma unroll
        for (int j = 0; j < 4; ++j) {
            int c = 4*kq + j;
            float mu  = g_cs1[bnslot*128 + c] * invn;
            float var = g_cs2[bnslot*128 + c] * invn - mu*mu;
            float aa  = gamma[c] * rsqrtf(var + 1e-5f);
            ca[j] = aa;
            cb[j] = beta[c] - mu*aa;
        }
    }

    int lane = tid & 31, g = lane >> 2, tg = lane & 3;
    int wid = tid >> 5, mw = wid & 1, nw = wid >> 1;
    bool lside = (nw < 2);

    // per-warp bias registers
    float2 bias[8];
    #pragma unroll
    for (int nn = 0; nn < 8; ++nn) {
        int col = nw*64 + nn*8 + 2*tg;
        const float* bsrc = (col < 128) ? bl : br;
        bias[nn] = make_float2(bsrc[col & 127], bsrc[(col & 127) + 1]);
    }

    // ldmatrix per-lane byte offsets
    int quad = lane >> 3, lr = lane & 7;
    unsigned laneA = (unsigned)((lr + ((quad & 1) ? 8 : 0)) * (SA_W*4) + ((quad & 2) ? 16 : 0));
    unsigned laneB = (unsigned)((lr + ((quad & 2) ? 8 : 0)) * (SA_W*4) + ((quad & 1) ? 16 : 0));
    const unsigned bB0  = sb + WB_WH + (unsigned)(nw*64)*(SA_W*4) + laneB; // Wh rows nw*64..
    const unsigned boB0 = sb + WB_WO + (unsigned)(nw*64)*(SA_W*4) + laneB; // Wo (lside only)
    const unsigned aRow = (unsigned)(mw*32)*(SA_W*4) + laneA;

    // ---- first tile: prefetch + split into buf0 ----
    int t = blockIdx.x;
    int cur = 0;
    bool have = true;                          // GRID_G < NTILE
    float4 pf[8];
    {
        #pragma unroll
        for (int i2 = 0; i2 < 8; ++i2) {
            int row = t*64 + i2*8 + rbase;
            pf[i2] = (row < NN) ? *(const float4*)(A + (size_t)row*128 + kq*4)
                                : make_float4(0.f,0.f,0.f,0.f);
        }
        unsigned* Ah = Ab;                     // buf0 hi
        unsigned* Al = Ab + 64*SA_W;           // buf0 lo
        #pragma unroll
        for (int i2 = 0; i2 < 8; ++i2) {
            int rl = i2*8 + rbase;
            float4 v = pf[i2];
            if (bnslot >= 0) {
                v.x = fmaxf(ca[0]*v.x + cb[0], 0.f);
                v.y = fmaxf(ca[1]*v.y + cb[1], 0.f);
                v.z = fmaxf(ca[2]*v.z + cb[2], 0.f);
                v.w = fmaxf(ca[3]*v.w + cb[3], 0.f);
            }
            unsigned h0,l0,h1,l1;
            cvt_hilo(v.x, v.y, h0, l0);
            cvt_hilo(v.z, v.w, h1, l1);
            *(uint2*)(Ah + rl*SA_W + 2*kq) = make_uint2(h0, h1);
            *(uint2*)(Al + rl*SA_W + 2*kq) = make_uint2(l0, l1);
        }
    }

    while (have) {
        __syncthreads();                       // buf(cur) (and W on iter 1) visible
        int tn = t + GRID_G;
        bool nhave = (tn < NTILE);

        // prefetch next A tile (LDG overlaps MMAs below)
        if (nhave) {
            #pragma unroll
            for (int i2 = 0; i2 < 8; ++i2) {
                int row = tn*64 + i2*8 + rbase;
                pf[i2] = (row < NN) ? *(const float4*)(A + (size_t)row*128 + kq*4)
                                    : make_float4(0.f,0.f,0.f,0.f);
            }
        }

        // ---- MMA on buf(cur) ----
        const unsigned aHi0 = sb + WB_A + (unsigned)cur*A_BUF_B + aRow;
        const unsigned aLo0 = aHi0 + A_LO_B;
        int r0 = t*64;

        float acc[2][8][4];
        #pragma unroll
        for (int mm = 0; mm < 2; ++mm)
            #pragma unroll
            for (int nn = 0; nn < 8; ++nn) {
                acc[mm][nn][0] = bias[nn].x; acc[mm][nn][1] = bias[nn].y;
                acc[mm][nn][2] = bias[nn].x; acc[mm][nn][3] = bias[nn].y;
            }

        #pragma unroll
        for (int kc = 0; kc < 8; ++kc) {
            unsigned koff = (unsigned)kc*32;
            unsigned ah[2][4], al[2][4], bh[4][4], bo[4][4];
            #pragma unroll
            for (int mm = 0; mm < 2; ++mm) {
                ldsm4(ah[mm], aHi0 + (unsigned)mm*(16*SA_W*4) + koff);
                ldsm4(al[mm], aLo0 + (unsigned)mm*(16*SA_W*4) + koff);
            }
            #pragma unroll
            for (int p = 0; p < 4; ++p)
                ldsm4(bh[p], bB0 + (unsigned)p*(16*SA_W*4) + koff);
            if (lside) {
                #pragma unroll
                for (int p = 0; p < 4; ++p)
                    ldsm4(bo[p], boB0 + (unsigned)p*(16*SA_W*4) + koff);
            }
            #pragma unroll
            for (int mm = 0; mm < 2; ++mm)
                #pragma unroll
                for (int nn = 0; nn < 8; ++nn)
                    mma16816(acc[mm][nn], ah[mm], &bh[nn>>1][(nn&1)*2]);
            #pragma unroll
            for (int mm = 0; mm < 2; ++mm)
                #pragma unroll
                for (int nn = 0; nn < 8; ++nn)
                    mma16816(acc[mm][nn], al[mm], &bh[nn>>1][(nn&1)*2]);
            if (lside) {
                #pragma unroll
                for (int mm = 0; mm < 2; ++mm)
                    #pragma unroll
                    for (int nn = 0; nn < 8; ++nn)
                        mma16816(acc[mm][nn], ah[mm], &bo[nn>>1][(nn&1)*2]);
            }
        }

        // ---- epilogue: cols<128 -> g_hl fp32, cols>=128 -> g_m2 fp16 ----
        #pragma unroll
        for (int mm = 0; mm < 2; ++mm) {
            int row = r0 + mw*32 + mm*16 + g;
            #pragma unroll
            for (int nn = 0; nn < 8; ++nn) {
                int col = nw*64 + nn*8 + 2*tg;
                if (col < 128) {
                    if (row < NN)
                        *(float2*)(g_hl + (size_t)row*128 + col) =
                            make_float2(acc[mm][nn][0], acc[mm][nn][1]);
                    if (row + 8 < NN)
                        *(float2*)(g_hl + (size_t)(row+8)*128 + col) =
                            make_float2(acc[mm][nn][2], acc[mm][nn][3]);
                } else {
                    int mc = (col - 128) >> 1;
                    if (row < NN) {
                        __half2 hh = __floats2half2_rn(acc[mm][nn][0], acc[mm][nn][1]);
                        g_m2[(size_t)row*64 + mc] = hh;
                    }
                    if (row + 8 < NN) {
                        __half2 hh = __floats2half2_rn(acc[mm][nn][2], acc[mm][nn][3]);
                        g_m2[(size_t)(row+8)*64 + mc] = hh;
                    }
                }
            }
        }

        // ---- split prefetched tile into the other buffer ----
        if (nhave) {
            unsigned* nAh = Ab + (cur^1)*(2*64*SA_W);
            unsigned* nAl = nAh + 64*SA_W;
            #pragma unroll
            for (int i2 = 0; i2 < 8; ++i2) {
                int rl = i2*8 + rbase;
                float4 v = pf[i2];
                if (bnslot >= 0) {
                    v.x = fmaxf(ca[0]*v.x + cb[0], 0.f);
                    v.y = fmaxf(ca[1]*v.y + cb[1], 0.f);
                    v.z = fmaxf(ca[2]*v.z + cb[2], 0.f);
                    v.w = fmaxf(ca[3]*v.w + cb[3], 0.f);
                }
                unsigned h0,l0,h1,l1;
                cvt_hilo(v.x, v.y, h0, l0);
                cvt_hilo(v.z, v.w, h1, l1);
                *(uint2*)(nAh + rl*SA_W + 2*kq) = make_uint2(h0, h1);
                *(uint2*)(nAl + rl*SA_W + 2*kq) = make_uint2(l0, l1);
            }
        }
        t = tn; cur ^= 1; have = nhave;
    }
}

// ---------------- gather-mean + combine + L2 norm + BN stats -----------------
__global__ void k_agg(int slot) {
    __shared__ float s1[128], s2[128];
    int tid = threadIdx.x;
    if (tid < 128) { s1[tid] = 0.f; s2[tid] = 0.f; }
    __syncthreads();
    int lane = tid & 31;
    int wid  = blockIdx.x*8 + (tid >> 5);
    int nw   = gridDim.x*8;
    float c1x=0,c1y=0,c1z=0,c1w=0, c2x=0,c2y=0,c2z=0,c2w=0;
    for (int node = wid; node < NN; node += nw) {
        int e0 = g_off[node], e1 = g_off[node+1];
        float ax=0, ay=0, az=0, aw=0;
        for (int e = e0; e < e1; ++e) {
            int srow = g_eid[e];
            uint2 raw = *(const uint2*)(g_m2 + (size_t)srow*64 + lane*2);
            float2 f0 = __half22float2(*reinterpret_cast<__half2*>(&raw.x));
            float2 f1 = __half22float2(*reinterpret_cast<__half2*>(&raw.y));
            ax += f0.x; ay += f0.y; az += f1.x; aw += f1.y;
        }
        float inv = 1.f / fmaxf((float)(e1 - e0), 1.f);
        float4 h = *(const float4*)(g_hl + (size_t)node*128 + lane*4);
        h.x += ax*inv; h.y += ay*inv; h.z += az*inv; h.w += aw*inv;
        float ss = h.x*h.x + h.y*h.y + h.z*h.z + h.w*h.w;
        #pragma unroll
        for (int o = 16; o > 0; o >>= 1) ss += __shfl_xor_sync(0xffffffffu, ss, o);
        float sc = 1.f / fmaxf(sqrtf(ss), 1e-12f);
        h.x *= sc; h.y *= sc; h.z *= sc; h.w *= sc;
        *(float4*)(g_hl + (size_t)node*128 + lane*4) = h;
        c1x += h.x; c1y += h.y; c1z += h.z; c1w += h.w;
        c2x += h.x*h.x; c2y += h.y*h.y; c2z += h.z*h.z; c2w += h.w*h.w;
    }
    atomicAdd(&s1[lane*4+0], c1x); atomicAdd(&s1[lane*4+1], c1y);
    atomicAdd(&s1[lane*4+2], c1z); atomicAdd(&s1[lane*4+3], c1w);
    atomicAdd(&s2[lane*4+0], c2x); atomicAdd(&s2[lane*4+1], c2y);
    atomicAdd(&s2[lane*4+2], c2z); atomicAdd(&s2[lane*4+3], c2w);
    __syncthreads();
    if (tid < 128) {
        atomicAdd(&g_cs1[slot*128 + tid], s1[tid]);
        atomicAdd(&g_cs2[slot*128 + tid], s2[tid]);
    }
}

// ---------------- pooling (BN+ReLU of last layer fused, 8-way split) ---------
__global__ void k_pool(const float* __restrict__ gamma, const float* __restrict__ beta) {
    int g = blockIdx.x, p = blockIdx.y, t = threadIdx.x;
    const float invn = 1.f / (float)NN;
    float mu  = g_cs1[2*128 + t] * invn;
    float var = g_cs2[2*128 + t] * invn - mu*mu;
    float a   = gamma[t] * rsqrtf(var + 1e-5f);
    float b   = beta[t] - mu*a;
    int s0 = g_gs[g], e0 = g_gs[g+1], len = e0 - s0;
    int s = s0 + (len * p) / 8;
    int e = s0 + (len * (p+1)) / 8;
    float acc = 0.f;
    for (int node = s; node < e; ++node)
        acc += fmaxf(a * g_hl[(size_t)node*128 + t] + b, 0.f);
    atomicAdd(&g_pool[g*128 + t], acc);
}

__global__ void k_head(const float* __restrict__ W1, const float* __restrict__ b1,
                       const float* __restrict__ W2, const float* __restrict__ b2,
                       float* __restrict__ out)
{
    __shared__ float ps[128], us[128], ls[OUTC], st[2];
    int g = blockIdx.x, t = threadIdx.x;
    float cg = (float)(g_gs[g+1] - g_gs[g]);
    ps[t] = g_pool[g*128 + t];
    __syncthreads();
    float u = b1[t] * cg;
    #pragma unroll 8
    for (int k = 0; k < 128; ++k) u += ps[k] * W1[t*128 + k];
    us[t] = u;
    __syncthreads();
    if (t < OUTC) {
        float l = b2[t] * cg;
        #pragma unroll 8
        for (int k = 0; k < 128; ++k) l += us[k] * W2[t*128 + k];
        ls[t] = l;
    }
    __syncthreads();
    if (t == 0) {
        float mx = -1e30f;
        for (int j = 0; j < OUTC; ++j) mx = fmaxf(mx, ls[j]);
        float se = 0.f;
        for (int j = 0; j < OUTC; ++j) se += expf(ls[j] - mx);
        st[0] = mx; st[1] = logf(se);
    }
    __syncthreads();
    if (t < OUTC) out[g*OUTC + t] = ls[t] - st[0] - st[1];
}

// ---------------- launch ------------------------------------------------------
extern "C" void kernel_launch(void* const* d_in, const int* in_sizes, int n_in,
                              void* d_out, int out_size)
{
    const float* x     = (const float*)d_in[0];
    const int*   ei    = (const int*)  d_in[1];
    const int*   batch = (const int*)  d_in[2];
    const float* Wl    = (const float*)d_in[3];
    const float* bl    = (const float*)d_in[4];
    const float* Wr    = (const float*)d_in[5];
    const float* br    = (const float*)d_in[6];
    const float* gamma = (const float*)d_in[7];
    const float* beta  = (const float*)d_in[8];
    const float* W1    = (const float*)d_in[9];
    const float* b1    = (const float*)d_in[10];
    const float* W2    = (const float*)d_in[11];
    const float* b2    = (const float*)d_in[12];
    float* out = (float*)d_out;

    const int* src = ei;
    const int* dst = ei + EE;

    cudaFuncSetAttribute(k_gemm_tc, cudaFuncAttributeMaxDynamicSharedMemorySize,
                         GEMM_SMEM_BYTES);

    k_zero   <<<391, 256>>>();                         // 0
    k_hist   <<<2344, 256>>>(dst);                     // 1
    k_scan1  <<<NB_SCAN, 1024>>>();                    // 2
    k_gemm_tc<<<GRID_G, 256, GEMM_SMEM_BYTES>>>(       // 3  <- ncu target (layer 0)
        x, Wl, Wr, bl, br, gamma, beta, -1);
    k_scan2p <<<1, 128>>>();                           // 4
    k_scan3  <<<391, 256>>>();                         // 5
    k_fill   <<<2344, 256>>>(src, dst);                // 6
    k_gstart <<<1, GG+1>>>(batch);                     // 7

    k_agg<<<1480, 256>>>(0);                           // 8
    k_gemm_tc<<<GRID_G, 256, GEMM_SMEM_BYTES>>>(       // 9  (layer 1, BN slot 0)
        nullptr, Wl + 1*HIDC*HIDC, Wr + 1*HIDC*HIDC, bl + 1*HIDC, br + 1*HIDC,
        gamma + 0*HIDC, beta + 0*HIDC, 0);
    k_agg<<<1480, 256>>>(1);                           // 10
    k_gemm_tc<<<GRID_G, 256, GEMM_SMEM_BYTES>>>(       // 11 (layer 2, BN slot 1)
        nullptr, Wl + 2*HIDC*HIDC, Wr + 2*HIDC*HIDC, bl + 2*HIDC, br + 2*HIDC,
        gamma + 1*HIDC, beta + 1*HIDC, 1);
    k_agg<<<1480, 256>>>(2);                           // 12

    k_pool<<<dim3(GG, 8), 128>>>(gamma + 2*HIDC, beta + 2*HIDC);  // 13
    k_head<<<GG, 128>>>(W1, b1, W2, b2, out);                     // 14
}